// round 1
// baseline (speedup 1.0000x reference)
#include <cuda_runtime.h>
#include <math.h>

#define L_DIM 128
#define D_DIM 64
#define M_DIM 256
#define TPB   256
#define TILE  16

// cen[m][d] transposed: cenT[d][m]
__device__ float g_cenT[D_DIM * M_DIM];

// ---------------------------------------------------------------------------
// Kernel A: cen = conf * (centroid_feats @ W + b), stored transposed [D][M]
// grid = M blocks, D threads
// ---------------------------------------------------------------------------
__global__ void cen_kernel(const float* __restrict__ cfeat,
                           const float* __restrict__ conf,
                           const float* __restrict__ W,
                           const float* __restrict__ bias)
{
    int m = blockIdx.x;
    int d = threadIdx.x;
    const float* row = cfeat + m * L_DIM;
    float acc = bias[d];
#pragma unroll 8
    for (int k = 0; k < L_DIM; k++)
        acc = fmaf(row[k], W[k * D_DIM + d], acc);
    g_cenT[d * M_DIM + m] = conf[m] * acc;
}

// ---------------------------------------------------------------------------
// Main kernel: per 16-row tile
//   Phase A: clu = feats @ W + b           (2x2 register-blocked, smem W)
//   Phase N: per-row L2-normalize scale
//   Phase B: warp handles 2 rows: v = clu . cen^T, integer exact distance,
//            masked softmax (warp shuffles), fused write of v*scale*attn
// ---------------------------------------------------------------------------
__global__ __launch_bounds__(TPB, 1)
void main_kernel(const int*   __restrict__ clu_c,
                 const int*   __restrict__ cen_c,
                 const float* __restrict__ feats,
                 const float* __restrict__ bias,
                 const float* __restrict__ Wg,
                 float*       __restrict__ out,
                 int N, int numTiles)
{
    extern __shared__ float sm[];
    float* W_s     = sm;                      // 8192
    float* cenT_s  = W_s + L_DIM * D_DIM;     // 16384
    float* b_s     = cenT_s + D_DIM * M_DIM;  // 64
    float* feats_s = b_s + D_DIM;             // TILE*128 = 2048
    float* clu_s   = feats_s + TILE * L_DIM;  // TILE*64  = 1024
    float* scale_s = clu_s + TILE * D_DIM;    // 16
    int*   cb_s    = (int*)(scale_s + TILE);  // 256
    int*   cx_s    = cb_s + M_DIM;
    int*   cy_s    = cx_s + M_DIM;
    int*   cz_s    = cy_s + M_DIM;
    int*   ec2_s   = cz_s + M_DIM;
    int*   rb_s    = ec2_s + M_DIM;           // 16 each
    int*   rx_s    = rb_s + TILE;
    int*   ry_s    = rx_s + TILE;
    int*   rz_s    = ry_s + TILE;
    int*   rn2_s   = rz_s + TILE;

    const int tid  = threadIdx.x;
    const int warp = tid >> 5;
    const int lane = tid & 31;

    // ---- one-time per-block staging ----
    for (int i = tid; i < L_DIM * D_DIM; i += TPB) W_s[i] = Wg[i];
    for (int i = tid; i < D_DIM * M_DIM; i += TPB) cenT_s[i] = g_cenT[i];
    if (tid < D_DIM) b_s[tid] = bias[tid];
    for (int m = tid; m < M_DIM; m += TPB) {
        int4 c = ((const int4*)cen_c)[m];
        cb_s[m] = c.x; cx_s[m] = c.y; cy_s[m] = c.z; cz_s[m] = c.w;
        ec2_s[m] = c.y * c.y + c.z * c.z + c.w * c.w;
    }
    __syncthreads();

    for (int tile = blockIdx.x; tile < numTiles; tile += gridDim.x) {
        const int row0 = tile * TILE;
        const int nval = min(TILE, N - row0);

        // ---- load feats tile (float4 coalesced) + row coords ----
        {
            const float4* fg = (const float4*)(feats + (long long)row0 * L_DIM);
            float4* fs = (float4*)feats_s;
            const int nf4 = nval * (L_DIM / 4);
            for (int i = tid; i < nf4; i += TPB) fs[i] = fg[i];
            if (tid < nval) {
                int4 c = ((const int4*)clu_c)[row0 + tid];
                rb_s[tid] = c.x; rx_s[tid] = c.y; ry_s[tid] = c.z; rz_s[tid] = c.w;
                rn2_s[tid] = c.y * c.y + c.z * c.z + c.w * c.w;
            }
        }
        __syncthreads();

        // ---- Phase A: clu GEMM, thread = 2 rows x 2 d ----
        {
            const int q = warp;          // rows 2q, 2q+1
            const int p = lane;          // d = 2p, 2p+1
            const float* f0 = feats_s + (2 * q) * L_DIM;
            const float* f1 = f0 + L_DIM;
            float a00 = b_s[2 * p], a01 = b_s[2 * p + 1];
            float a10 = a00,        a11 = a01;
#pragma unroll 4
            for (int k = 0; k < L_DIM; k++) {
                float x0 = f0[k], x1 = f1[k];
                float2 w2 = *(const float2*)(W_s + k * D_DIM + 2 * p);
                a00 = fmaf(x0, w2.x, a00); a01 = fmaf(x0, w2.y, a01);
                a10 = fmaf(x1, w2.x, a10); a11 = fmaf(x1, w2.y, a11);
            }
            *(float2*)(clu_s + (2 * q) * D_DIM + 2 * p)     = make_float2(a00, a01);
            *(float2*)(clu_s + (2 * q + 1) * D_DIM + 2 * p) = make_float2(a10, a11);
        }
        __syncthreads();

        // ---- Phase N: per-row normalize scale ----
        if (tid < TILE) {
            const float* cr = clu_s + tid * D_DIM;
            float s = 0.f;
#pragma unroll 8
            for (int d = 0; d < D_DIM; d++) s = fmaf(cr[d], cr[d], s);
            scale_s[tid] = 1.0f / fmaxf(sqrtf(s), 1e-12f);
        }
        __syncthreads();

        // ---- Phase B: warp handles rows 2*warp, 2*warp+1 ----
        float vA[8], vB[8];
#pragma unroll
        for (int j = 0; j < 8; j++) { vA[j] = 0.f; vB[j] = 0.f; }
        {
            const float* cAp = clu_s + (2 * warp) * D_DIM;
            const float* cBp = cAp + D_DIM;
#pragma unroll 2
            for (int d = 0; d < D_DIM; d++) {
                const float a = cAp[d];
                const float bb = cBp[d];
                const float* ce = cenT_s + d * M_DIM + lane;
#pragma unroll
                for (int j = 0; j < 8; j++) {
                    float c = ce[j * 32];
                    vA[j] = fmaf(a,  c, vA[j]);
                    vB[j] = fmaf(bb, c, vB[j]);
                }
            }
        }

#pragma unroll
        for (int rr = 0; rr < 2; rr++) {
            const int r = 2 * warp + rr;
            const int row = row0 + r;
            if (row < N) {
                const int rb = rb_s[r], rx = rx_s[r], ry = ry_s[r], rz = rz_s[r];
                const int rn2 = rn2_s[r];
                const float scale = scale_s[r];
                float logit[8];
                float maxl = -3.0e38f;
#pragma unroll
                for (int j = 0; j < 8; j++) {
                    const int m = j * 32 + lane;
                    // exact integer squared distance (coords < 1024 => exact in int32,
                    // matching the reference's exact fp32 expansion)
                    const int dot = rx * cx_s[m] + ry * cy_s[m] + rz * cz_s[m];
                    const int d2  = rn2 + ec2_s[m] - 2 * dot;
                    const float dist = fmaxf(sqrtf((float)d2), 0.1f);
                    const bool valid = (cb_s[m] == rb);
                    logit[j] = valid ? -dist : -3.0e38f;
                    maxl = fmaxf(maxl, logit[j]);
                }
#pragma unroll
                for (int off = 16; off; off >>= 1)
                    maxl = fmaxf(maxl, __shfl_xor_sync(0xffffffffu, maxl, off));

                float e[8];
                float sum = 0.f;
#pragma unroll
                for (int j = 0; j < 8; j++) {
                    e[j] = (logit[j] > -1.0e38f) ? __expf(logit[j] - maxl) : 0.f;
                    sum += e[j];
                }
#pragma unroll
                for (int off = 16; off; off >>= 1)
                    sum += __shfl_xor_sync(0xffffffffu, sum, off);

                const float rinv = (sum > 0.f) ? (1.0f / sum) : 0.f;
                float* orow = out + (long long)row * M_DIM;
#pragma unroll
                for (int j = 0; j < 8; j++) {
                    const float vv = (rr == 0) ? vA[j] : vB[j];
                    orow[j * 32 + lane] = vv * scale * e[j] * rinv;
                }
            }
        }
        __syncthreads();   // protect rb_s/feats_s/clu_s before next tile's loads
    }
}

// ---------------------------------------------------------------------------
extern "C" void kernel_launch(void* const* d_in, const int* in_sizes, int n_in,
                              void* d_out, int out_size)
{
    const int*   clu_c = (const int*)  d_in[0];
    const int*   cen_c = (const int*)  d_in[1];
    const float* feats = (const float*)d_in[2];
    const float* cfeat = (const float*)d_in[3];
    const float* conf  = (const float*)d_in[4];
    const float* W     = (const float*)d_in[5];
    const float* bias  = (const float*)d_in[6];
    float* out = (float*)d_out;

    const int N = in_sizes[2] / L_DIM;
    const int numTiles = (N + TILE - 1) / TILE;

    // smem: floats 8192+16384+64+2048+1024+16 = 27728, ints 5*256+5*16 = 1360
    const size_t SMEM = (size_t)(27728 + 1360) * 4;  // 116352 B

    cen_kernel<<<M_DIM, D_DIM>>>(cfeat, conf, W, bias);

    cudaFuncSetAttribute(main_kernel,
                         cudaFuncAttributeMaxDynamicSharedMemorySize, (int)SMEM);
    main_kernel<<<592, TPB, SMEM>>>(clu_c, cen_c, feats, bias, W, out, N, numTiles);
}